// round 2
// baseline (speedup 1.0000x reference)
#include <cuda_runtime.h>
#include <math.h>

#define BSZ 2
#define SEQ 2048
#define DIM 1024
#define NH  16
#define HDIM 64
#define MTOT (BSZ * SEQ)       // 4096
#define QKV_N (3 * DIM)        // 3072

// Scratch (module-load allocation, not kernel_launch allocation)
static __device__ float g_qkv[(size_t)MTOT * QKV_N];   // ~50 MB
static __device__ float g_att[(size_t)MTOT * DIM];     // ~17 MB

// ---------------------------------------------------------------------------
// SGEMM: C[M,N] = A[M,K] @ B[K,N], row-major, M%128==0, N%128==0, K%16==0
// 128x128 block tile, BK=16, 256 threads, 8x8 per-thread register tile.
// ---------------------------------------------------------------------------
__global__ __launch_bounds__(256)
void sgemm128(const float* __restrict__ A, const float* __restrict__ B,
              float* __restrict__ C, int M, int N, int K) {
    __shared__ float As[16][128];
    __shared__ float Bs[16][128];

    const int tid = threadIdx.x;
    const int bm = blockIdx.y * 128;
    const int bn = blockIdx.x * 128;
    const int tm = (tid >> 4) << 3;   // 0..120 step 8
    const int tn = (tid & 15) << 3;

    float acc[8][8];
#pragma unroll
    for (int i = 0; i < 8; ++i)
#pragma unroll
        for (int j = 0; j < 8; ++j) acc[i][j] = 0.f;

    for (int k0 = 0; k0 < K; k0 += 16) {
        __syncthreads();
#pragma unroll
        for (int t = 0; t < 2; ++t) {
            int f = tid * 2 + t;                 // 0..511
            // A tile: 128 rows x 16 cols
            int ar = f >> 2, ac = (f & 3) << 2;
            float4 a4 = *(const float4*)&A[(size_t)(bm + ar) * K + k0 + ac];
            As[ac + 0][ar] = a4.x;
            As[ac + 1][ar] = a4.y;
            As[ac + 2][ar] = a4.z;
            As[ac + 3][ar] = a4.w;
            // B tile: 16 rows x 128 cols
            int br = f >> 5, bc = (f & 31) << 2;
            *(float4*)&Bs[br][bc] = *(const float4*)&B[(size_t)(k0 + br) * N + bn + bc];
        }
        __syncthreads();
#pragma unroll
        for (int k = 0; k < 16; ++k) {
            float a[8], b[8];
            *(float4*)&a[0] = *(float4*)&As[k][tm];
            *(float4*)&a[4] = *(float4*)&As[k][tm + 4];
            *(float4*)&b[0] = *(float4*)&Bs[k][tn];
            *(float4*)&b[4] = *(float4*)&Bs[k][tn + 4];
#pragma unroll
            for (int i = 0; i < 8; ++i)
#pragma unroll
                for (int j = 0; j < 8; ++j) acc[i][j] += a[i] * b[j];
        }
    }

#pragma unroll
    for (int i = 0; i < 8; ++i) {
        float4* dst = (float4*)&C[(size_t)(bm + tm + i) * N + bn + tn];
        dst[0] = make_float4(acc[i][0], acc[i][1], acc[i][2], acc[i][3]);
        dst[1] = make_float4(acc[i][4], acc[i][5], acc[i][6], acc[i][7]);
    }
}

// ---------------------------------------------------------------------------
// Flash attention over fp32 qkv buffer laid out [B,S,3,H,HD].
// One block = 64 queries for one (b,h). K/V streamed in 32-row tiles.
// 128 threads: ty=tid>>3 (16, 4 rows each), tx=tid&7 (8, 4 score cols / 8 O cols).
// Row reductions via shfl_xor within 8-lane groups.
// ---------------------------------------------------------------------------
__global__ __launch_bounds__(128)
void flash_attn(const float* __restrict__ qkv, float* __restrict__ out) {
    __shared__ float Qs[64][65];
    __shared__ float Ks[32][65];
    __shared__ float Vs[32][65];
    __shared__ float Ps[64][33];

    const int tid = threadIdx.x;
    const int tx = tid & 7;
    const int ty = tid >> 3;
    const int qt = blockIdx.x;
    const int h  = blockIdx.y;
    const int b  = blockIdx.z;

    const float scale = 0.125f;  // 1/sqrt(64)

    // Load Q tile (scaled): 64 rows x 64 cols
    const float* qb = qkv + ((size_t)(b * SEQ + qt * 64)) * QKV_N + h * HDIM;
#pragma unroll
    for (int t = 0; t < 8; ++t) {
        int f = tid + t * 128;            // 0..1023 float4s
        int r = f >> 4, c = (f & 15) << 2;
        float4 v = *(const float4*)(qb + (size_t)r * QKV_N + c);
        Qs[r][c + 0] = v.x * scale;
        Qs[r][c + 1] = v.y * scale;
        Qs[r][c + 2] = v.z * scale;
        Qs[r][c + 3] = v.w * scale;
    }

    float m[4], l[4], o[4][8];
#pragma unroll
    for (int i = 0; i < 4; ++i) {
        m[i] = -INFINITY;
        l[i] = 0.f;
#pragma unroll
        for (int d = 0; d < 8; ++d) o[i][d] = 0.f;
    }

    for (int kt = 0; kt < SEQ / 32; ++kt) {
        const float* kb = qkv + ((size_t)(b * SEQ + kt * 32)) * QKV_N + DIM + h * HDIM;
        const float* vb = kb + DIM;
        __syncthreads();   // previous PV done reading Ks/Vs/Ps
#pragma unroll
        for (int t = 0; t < 4; ++t) {
            int f = tid + t * 128;        // 0..511 float4s
            int r = f >> 4, c = (f & 15) << 2;
            float4 k4 = *(const float4*)(kb + (size_t)r * QKV_N + c);
            Ks[r][c + 0] = k4.x; Ks[r][c + 1] = k4.y;
            Ks[r][c + 2] = k4.z; Ks[r][c + 3] = k4.w;
            float4 v4 = *(const float4*)(vb + (size_t)r * QKV_N + c);
            Vs[r][c + 0] = v4.x; Vs[r][c + 1] = v4.y;
            Vs[r][c + 2] = v4.z; Vs[r][c + 3] = v4.w;
        }
        __syncthreads();

        // S = Q @ K^T for this tile: each thread 4x4
        float s[4][4];
#pragma unroll
        for (int i = 0; i < 4; ++i)
#pragma unroll
            for (int j = 0; j < 4; ++j) s[i][j] = 0.f;

#pragma unroll
        for (int k = 0; k < 64; ++k) {
            float qv[4], kv[4];
#pragma unroll
            for (int i = 0; i < 4; ++i) qv[i] = Qs[ty * 4 + i][k];
#pragma unroll
            for (int j = 0; j < 4; ++j) kv[j] = Ks[tx * 4 + j][k];
#pragma unroll
            for (int i = 0; i < 4; ++i)
#pragma unroll
                for (int j = 0; j < 4; ++j) s[i][j] += qv[i] * kv[j];
        }

        // Online softmax per row
#pragma unroll
        for (int i = 0; i < 4; ++i) {
            float rm = fmaxf(fmaxf(s[i][0], s[i][1]), fmaxf(s[i][2], s[i][3]));
#pragma unroll
            for (int off = 4; off >= 1; off >>= 1)
                rm = fmaxf(rm, __shfl_xor_sync(0xffffffffu, rm, off));
            float mn = fmaxf(m[i], rm);
            float corr = __expf(m[i] - mn);
            float rs = 0.f;
#pragma unroll
            for (int j = 0; j < 4; ++j) {
                s[i][j] = __expf(s[i][j] - mn);
                rs += s[i][j];
            }
#pragma unroll
            for (int off = 4; off >= 1; off >>= 1)
                rs += __shfl_xor_sync(0xffffffffu, rs, off);
            l[i] = l[i] * corr + rs;
            m[i] = mn;
#pragma unroll
            for (int d = 0; d < 8; ++d) o[i][d] *= corr;
#pragma unroll
            for (int j = 0; j < 4; ++j) Ps[ty * 4 + i][tx * 4 + j] = s[i][j];
        }
        __syncthreads();

        // O += P @ V : each thread rows (4ty..+3), cols (8tx..+7)
#pragma unroll
        for (int j = 0; j < 32; ++j) {
            float pv[4], vv[8];
#pragma unroll
            for (int i = 0; i < 4; ++i) pv[i] = Ps[ty * 4 + i][j];
#pragma unroll
            for (int d = 0; d < 8; ++d) vv[d] = Vs[j][tx * 8 + d];
#pragma unroll
            for (int i = 0; i < 4; ++i)
#pragma unroll
                for (int d = 0; d < 8; ++d) o[i][d] += pv[i] * vv[d];
        }
    }

    // Epilogue: normalize and write to g_att [B,S,H,HD]
    float* ob = out + ((size_t)(b * SEQ + qt * 64)) * DIM + h * HDIM;
#pragma unroll
    for (int i = 0; i < 4; ++i) {
        float inv = 1.f / l[i];
#pragma unroll
        for (int d = 0; d < 8; ++d)
            ob[(size_t)(ty * 4 + i) * DIM + tx * 8 + d] = o[i][d] * inv;
    }
}

// ---------------------------------------------------------------------------
extern "C" void kernel_launch(void* const* d_in, const int* in_sizes, int n_in,
                              void* d_out, int out_size) {
    const float* x     = (const float*)d_in[0];   // [B,S,DIM]
    const float* Wqkv  = (const float*)d_in[1];   // [DIM, 3*DIM]
    const float* Wproj = (const float*)d_in[2];   // [DIM, DIM]
    float* out = (float*)d_out;                   // [B,S,DIM]

    float* qkv; cudaGetSymbolAddress((void**)&qkv, g_qkv);
    float* att; cudaGetSymbolAddress((void**)&att, g_att);

    // 1) qkv = x @ Wqkv  : [4096,1024] @ [1024,3072]
    {
        dim3 grid(QKV_N / 128, MTOT / 128);
        sgemm128<<<grid, 256>>>(x, Wqkv, qkv, MTOT, QKV_N, DIM);
    }
    // 2) attention -> att [4096,1024]
    {
        dim3 grid(SEQ / 64, NH, BSZ);
        flash_attn<<<grid, 128>>>(qkv, att);
    }
    // 3) out = att @ Wproj : [4096,1024] @ [1024,1024]
    {
        dim3 grid(DIM / 128, MTOT / 128);
        sgemm128<<<grid, 256>>>(att, Wproj, out, MTOT, DIM, DIM);
    }
}

// round 5
// speedup vs baseline: 1.5864x; 1.5864x over previous
#include <cuda_runtime.h>
#include <cuda_bf16.h>
#include <math.h>
#include <stdint.h>

#define BSZ 2
#define SEQ 2048
#define DIM 1024
#define NH  16
#define HDIM 64
#define MTOT (BSZ * SEQ)       // 4096
#define QKV_N (3 * DIM)        // 3072

// ---------------------------------------------------------------------------
// Scratch (module-load allocation, not kernel_launch allocation)
// ---------------------------------------------------------------------------
static __device__ float g_qkv[(size_t)MTOT * QKV_N];             // fp32 qkv
static __device__ float g_att[(size_t)MTOT * DIM];               // fp32 attn out
static __device__ __nv_bfloat16 g_xhi[(size_t)MTOT * DIM];
static __device__ __nv_bfloat16 g_xlo[(size_t)MTOT * DIM];
static __device__ __nv_bfloat16 g_wqkvT_hi[(size_t)QKV_N * DIM]; // [N,K]
static __device__ __nv_bfloat16 g_wqkvT_lo[(size_t)QKV_N * DIM];
static __device__ __nv_bfloat16 g_wprojT_hi[(size_t)DIM * DIM];
static __device__ __nv_bfloat16 g_wprojT_lo[(size_t)DIM * DIM];
static __device__ __nv_bfloat16 g_atthi[(size_t)MTOT * DIM];
static __device__ __nv_bfloat16 g_attlo[(size_t)MTOT * DIM];

// ---------------------------------------------------------------------------
// Warp MMA helpers (sm_80+ baseline — no 'a'-gated features)
// ---------------------------------------------------------------------------
__device__ __forceinline__ uint32_t smem_u32(const void* p) {
    uint32_t a;
    asm("{ .reg .u64 t; cvta.to.shared.u64 t, %1; cvt.u32.u64 %0, t; }"
        : "=r"(a) : "l"(p));
    return a;
}

__device__ __forceinline__ void ldsm_x4(uint32_t addr, uint32_t* r) {
    asm volatile("ldmatrix.sync.aligned.m8n8.x4.shared.b16 {%0,%1,%2,%3}, [%4];"
                 : "=r"(r[0]), "=r"(r[1]), "=r"(r[2]), "=r"(r[3]) : "r"(addr));
}

__device__ __forceinline__ void mma_bf16(float* d, const uint32_t* a, const uint32_t* b) {
    asm volatile(
        "mma.sync.aligned.m16n8k16.row.col.f32.bf16.bf16.f32 "
        "{%0,%1,%2,%3}, {%4,%5,%6,%7}, {%8,%9}, {%0,%1,%2,%3};"
        : "+f"(d[0]), "+f"(d[1]), "+f"(d[2]), "+f"(d[3])
        : "r"(a[0]), "r"(a[1]), "r"(a[2]), "r"(a[3]), "r"(b[0]), "r"(b[1]));
}

// ---------------------------------------------------------------------------
// Split conversion kernels
// ---------------------------------------------------------------------------
__global__ void split_rm(const float* __restrict__ in, __nv_bfloat16* __restrict__ hi,
                         __nv_bfloat16* __restrict__ lo, int n4) {
    int i = blockIdx.x * 256 + threadIdx.x;
    if (i >= n4) return;
    float4 v = ((const float4*)in)[i];
    __nv_bfloat16 h0 = __float2bfloat16(v.x), h1 = __float2bfloat16(v.y);
    __nv_bfloat16 h2 = __float2bfloat16(v.z), h3 = __float2bfloat16(v.w);
    __nv_bfloat162 H0 = __nv_bfloat162(h0, h1), H1 = __nv_bfloat162(h2, h3);
    __nv_bfloat162 L0 = __nv_bfloat162(__float2bfloat16(v.x - __bfloat162float(h0)),
                                       __float2bfloat16(v.y - __bfloat162float(h1)));
    __nv_bfloat162 L1 = __nv_bfloat162(__float2bfloat16(v.z - __bfloat162float(h2)),
                                       __float2bfloat16(v.w - __bfloat162float(h3)));
    ((__nv_bfloat162*)hi)[i * 2 + 0] = H0;
    ((__nv_bfloat162*)hi)[i * 2 + 1] = H1;
    ((__nv_bfloat162*)lo)[i * 2 + 0] = L0;
    ((__nv_bfloat162*)lo)[i * 2 + 1] = L1;
}

// in: [K,N] fp32 row-major  ->  out hi/lo: [N,K] bf16 row-major (transposed split)
__global__ void split_tr(const float* __restrict__ in, __nv_bfloat16* __restrict__ hi,
                         __nv_bfloat16* __restrict__ lo, int K, int N) {
    __shared__ float t[32][33];
    int n0 = blockIdx.x * 32, k0 = blockIdx.y * 32;
    int tx = threadIdx.x, ty = threadIdx.y;
#pragma unroll
    for (int i = ty; i < 32; i += 8)
        t[i][tx] = in[(size_t)(k0 + i) * N + n0 + tx];
    __syncthreads();
#pragma unroll
    for (int i = ty; i < 32; i += 8) {
        float x = t[tx][i];   // element (k0+tx, n0+i)
        __nv_bfloat16 h = __float2bfloat16(x);
        size_t idx = (size_t)(n0 + i) * K + k0 + tx;
        hi[idx] = h;
        lo[idx] = __float2bfloat16(x - __bfloat162float(h));
    }
}

// ---------------------------------------------------------------------------
// Split-bf16 mma.sync GEMM: C[M,N] = A[M,K] @ Bt[N,K]^T   (fp32 result)
// A = Ahi+Alo, Bt = Bthi+Btlo (bf16). 3 MMAs per product (skip lo*lo).
// CTA tile 128x128, BK=32, 256 threads = 8 warps (2m x 4n), warp tile 64x32.
// Smem rows padded to 40 bf16 (80 B) -> conflict-free ldmatrix phases.
// Double-buffered smem, register prefetch of the next chunk.
// ---------------------------------------------------------------------------
#define GT_ROWP    40                          // padded row length (bf16)
#define GT_TILE_E  (128 * GT_ROWP)             // 5120 bf16 per tile
#define GT_TILE_B  (GT_TILE_E * 2)             // 10240 bytes
#define GT_STAGE_B (4 * GT_TILE_B)             // Ahi,Alo,Bhi,Blo = 40960
#define GT_SMEM_SZ (2 * GT_STAGE_B)            // 81920

__global__ __launch_bounds__(256)
void gemm_mma3(const __nv_bfloat16* __restrict__ Ahi, const __nv_bfloat16* __restrict__ Alo,
               const __nv_bfloat16* __restrict__ Bthi, const __nv_bfloat16* __restrict__ Btlo,
               float* __restrict__ C, int M, int N, int K) {
    extern __shared__ char smem[];
    const uint32_t sbase = smem_u32(smem);
    const int tid = threadIdx.x;
    const int wid = tid >> 5;
    const int lane = tid & 31;
    const int wm = wid >> 2;          // 0..1  (64 rows each)
    const int wn = wid & 3;           // 0..3  (32 cols each)
    const int grp = lane >> 2;        // 0..7
    const int qid = lane & 3;         // 0..3
    const int bm = blockIdx.y * 128;
    const int bn = blockIdx.x * 128;
    const int NC = K >> 5;            // chunks of 32

    const __nv_bfloat16* srcs[4];
    srcs[0] = Ahi + (size_t)bm * K;
    srcs[1] = Alo + (size_t)bm * K;
    srcs[2] = Bthi + (size_t)bn * K;
    srcs[3] = Btlo + (size_t)bn * K;

    // per-thread gmem slots: 8 float4 (2 per tile), f = tid + j*256 (j=0..1)
    // r = f>>2 (0..127), c8 = (f&3)*8 (0..24)
    float4 pf[8];
    auto load_g = [&](int c) {
        int k0 = c << 5;
#pragma unroll
        for (int i = 0; i < 8; ++i) {
            int t = i >> 1;
            int f = tid + (i & 1) * 256;
            int r = f >> 2, c8 = (f & 3) << 3;
            pf[i] = *(const float4*)(srcs[t] + (size_t)r * K + k0 + c8);
        }
    };
    auto store_s = [&](int buf) {
        char* dst = smem + buf * GT_STAGE_B;
#pragma unroll
        for (int i = 0; i < 8; ++i) {
            int t = i >> 1;
            int f = tid + (i & 1) * 256;
            int r = f >> 2, c8 = (f & 3) << 3;
            *(float4*)(dst + t * GT_TILE_B + (r * GT_ROWP + c8) * 2) = pf[i];
        }
    };

    float acc[4][4][4];
#pragma unroll
    for (int i = 0; i < 4; ++i)
#pragma unroll
        for (int j = 0; j < 4; ++j)
#pragma unroll
            for (int q = 0; q < 4; ++q) acc[i][j][q] = 0.f;

    // ldmatrix lane-address components (element offsets within a tile)
    // A: row = wm*64 + mt*16 + (lane&15), col = ks*16 + (lane>>4)*8
    const int a_row = wm * 64 + (lane & 15);
    const int a_col = (lane >> 4) << 3;
    // B: row = wn*32 + p*16 + ((lane>>4)&1)*8 + (lane&7), col = ks*16 + ((lane>>3)&1)*8
    const int b_row = wn * 32 + (((lane >> 4) & 1) << 3) + (lane & 7);
    const int b_col = ((lane >> 3) & 1) << 3;

    load_g(0);
    store_s(0);
    __syncthreads();

    for (int c = 0; c < NC; ++c) {
        if (c + 1 < NC) load_g(c + 1);

        const uint32_t st = sbase + (c & 1) * GT_STAGE_B;
        const uint32_t sAh = st;
        const uint32_t sAl = st + GT_TILE_B;
        const uint32_t sBh = st + 2 * GT_TILE_B;
        const uint32_t sBl = st + 3 * GT_TILE_B;

#pragma unroll
        for (int ks = 0; ks < 2; ++ks) {
            uint32_t ah[4][4], al[4][4], bh[2][4], bl[2][4];
#pragma unroll
            for (int mt = 0; mt < 4; ++mt) {
                uint32_t off = ((a_row + mt * 16) * GT_ROWP + ks * 16 + a_col) * 2;
                ldsm_x4(sAh + off, ah[mt]);
                ldsm_x4(sAl + off, al[mt]);
            }
#pragma unroll
            for (int p = 0; p < 2; ++p) {
                uint32_t off = ((b_row + p * 16) * GT_ROWP + ks * 16 + b_col) * 2;
                ldsm_x4(sBh + off, bh[p]);
                ldsm_x4(sBl + off, bl[p]);
            }
#pragma unroll
            for (int mt = 0; mt < 4; ++mt) {
#pragma unroll
                for (int nt = 0; nt < 4; ++nt) {
                    const uint32_t* Bh = &bh[nt >> 1][(nt & 1) * 2];
                    const uint32_t* Bl = &bl[nt >> 1][(nt & 1) * 2];
                    mma_bf16(acc[mt][nt], ah[mt], Bh);
                    mma_bf16(acc[mt][nt], ah[mt], Bl);
                    mma_bf16(acc[mt][nt], al[mt], Bh);
                }
            }
        }

        __syncthreads();
        if (c + 1 < NC) {
            store_s((c + 1) & 1);
            __syncthreads();
        }
    }

    // Epilogue: fragment layout m16n8 f32: c0,c1 -> (grp, 2q),(grp,2q+1); c2,c3 -> row+8
#pragma unroll
    for (int mt = 0; mt < 4; ++mt) {
#pragma unroll
        for (int nt = 0; nt < 4; ++nt) {
            int row = bm + wm * 64 + mt * 16 + grp;
            int col = bn + wn * 32 + nt * 8 + qid * 2;
            *(float2*)&C[(size_t)row * N + col] = make_float2(acc[mt][nt][0], acc[mt][nt][1]);
            *(float2*)&C[(size_t)(row + 8) * N + col] = make_float2(acc[mt][nt][2], acc[mt][nt][3]);
        }
    }
}

// ---------------------------------------------------------------------------
// Flash attention over fp32 qkv buffer [B,S,3,H,HD] -> out [B,S,H*HD].
// One block = 64 queries for one (b,h). K/V streamed in 32-row tiles.
// Vectorized (float4) smem traffic; paddings are 16B multiples.
// ---------------------------------------------------------------------------
__global__ __launch_bounds__(128)
void flash_attn(const float* __restrict__ qkv, float* __restrict__ out) {
    __shared__ float Qs[64][68];
    __shared__ float Ks[32][68];
    __shared__ float Vs[32][68];
    __shared__ float Ps[64][36];

    const int tid = threadIdx.x;
    const int tx = tid & 7;
    const int ty = tid >> 3;
    const int qt = blockIdx.x;
    const int h  = blockIdx.y;
    const int b  = blockIdx.z;

    const float scale = 0.125f;  // 1/sqrt(64)

    const float* qb = qkv + ((size_t)(b * SEQ + qt * 64)) * QKV_N + h * HDIM;
#pragma unroll
    for (int t = 0; t < 8; ++t) {
        int f = tid + t * 128;            // 0..1023 float4s
        int r = f >> 4, c = (f & 15) << 2;
        float4 v = *(const float4*)(qb + (size_t)r * QKV_N + c);
        Qs[r][c + 0] = v.x * scale;
        Qs[r][c + 1] = v.y * scale;
        Qs[r][c + 2] = v.z * scale;
        Qs[r][c + 3] = v.w * scale;
    }

    float m[4], l[4], o[4][8];
#pragma unroll
    for (int i = 0; i < 4; ++i) {
        m[i] = -INFINITY;
        l[i] = 0.f;
#pragma unroll
        for (int d = 0; d < 8; ++d) o[i][d] = 0.f;
    }

    for (int kt = 0; kt < SEQ / 32; ++kt) {
        const float* kb = qkv + ((size_t)(b * SEQ + kt * 32)) * QKV_N + DIM + h * HDIM;
        const float* vb = kb + DIM;
        __syncthreads();
#pragma unroll
        for (int t = 0; t < 4; ++t) {
            int f = tid + t * 128;        // 0..511 float4s
            int r = f >> 4, c = (f & 15) << 2;
            float4 k4 = *(const float4*)(kb + (size_t)r * QKV_N + c);
            Ks[r][c + 0] = k4.x; Ks[r][c + 1] = k4.y;
            Ks[r][c + 2] = k4.z; Ks[r][c + 3] = k4.w;
            float4 v4 = *(const float4*)(vb + (size_t)r * QKV_N + c);
            Vs[r][c + 0] = v4.x; Vs[r][c + 1] = v4.y;
            Vs[r][c + 2] = v4.z; Vs[r][c + 3] = v4.w;
        }
        __syncthreads();

        // S = Q @ K^T : each thread 4x4, float4 along k
        float s[4][4];
#pragma unroll
        for (int i = 0; i < 4; ++i)
#pragma unroll
            for (int j = 0; j < 4; ++j) s[i][j] = 0.f;

#pragma unroll
        for (int k4 = 0; k4 < 16; ++k4) {
            float4 qv[4], kv[4];
#pragma unroll
            for (int i = 0; i < 4; ++i) qv[i] = *(float4*)&Qs[ty * 4 + i][k4 * 4];
#pragma unroll
            for (int j = 0; j < 4; ++j) kv[j] = *(float4*)&Ks[tx * 4 + j][k4 * 4];
#pragma unroll
            for (int i = 0; i < 4; ++i)
#pragma unroll
                for (int j = 0; j < 4; ++j)
                    s[i][j] += qv[i].x * kv[j].x + qv[i].y * kv[j].y +
                               qv[i].z * kv[j].z + qv[i].w * kv[j].w;
        }

        // Online softmax per row
#pragma unroll
        for (int i = 0; i < 4; ++i) {
            float rm = fmaxf(fmaxf(s[i][0], s[i][1]), fmaxf(s[i][2], s[i][3]));
#pragma unroll
            for (int off = 4; off >= 1; off >>= 1)
                rm = fmaxf(rm, __shfl_xor_sync(0xffffffffu, rm, off));
            float mn = fmaxf(m[i], rm);
            float corr = __expf(m[i] - mn);
            float rs = 0.f;
#pragma unroll
            for (int j = 0; j < 4; ++j) {
                s[i][j] = __expf(s[i][j] - mn);
                rs += s[i][j];
            }
#pragma unroll
            for (int off = 4; off >= 1; off >>= 1)
                rs += __shfl_xor_sync(0xffffffffu, rs, off);
            l[i] = l[i] * corr + rs;
            m[i] = mn;
#pragma unroll
            for (int d = 0; d < 8; ++d) o[i][d] *= corr;
#pragma unroll
            for (int j = 0; j < 4; ++j) Ps[ty * 4 + i][tx * 4 + j] = s[i][j];
        }
        __syncthreads();

        // O += P @ V : vectorized over j (4 at a time)
#pragma unroll
        for (int j4 = 0; j4 < 8; ++j4) {
            float4 p4[4];
#pragma unroll
            for (int i = 0; i < 4; ++i) p4[i] = *(float4*)&Ps[ty * 4 + i][j4 * 4];
            float vv[4][8];
#pragma unroll
            for (int jj = 0; jj < 4; ++jj) {
                float4 a = *(float4*)&Vs[j4 * 4 + jj][tx * 8];
                float4 bq = *(float4*)&Vs[j4 * 4 + jj][tx * 8 + 4];
                vv[jj][0] = a.x;  vv[jj][1] = a.y;  vv[jj][2] = a.z;  vv[jj][3] = a.w;
                vv[jj][4] = bq.x; vv[jj][5] = bq.y; vv[jj][6] = bq.z; vv[jj][7] = bq.w;
            }
#pragma unroll
            for (int i = 0; i < 4; ++i) {
                float pj[4] = {p4[i].x, p4[i].y, p4[i].z, p4[i].w};
#pragma unroll
                for (int jj = 0; jj < 4; ++jj)
#pragma unroll
                    for (int d = 0; d < 8; ++d) o[i][d] += pj[jj] * vv[jj][d];
            }
        }
    }

    float* ob = out + ((size_t)(b * SEQ + qt * 64)) * DIM + h * HDIM;
#pragma unroll
    for (int i = 0; i < 4; ++i) {
        float inv = 1.f / l[i];
        float4* dst = (float4*)&ob[(size_t)(ty * 4 + i) * DIM + tx * 8];
        dst[0] = make_float4(o[i][0] * inv, o[i][1] * inv, o[i][2] * inv, o[i][3] * inv);
        dst[1] = make_float4(o[i][4] * inv, o[i][5] * inv, o[i][6] * inv, o[i][7] * inv);
    }
}

// ---------------------------------------------------------------------------
extern "C" void kernel_launch(void* const* d_in, const int* in_sizes, int n_in,
                              void* d_out, int out_size) {
    const float* x     = (const float*)d_in[0];   // [B,S,DIM]
    const float* Wqkv  = (const float*)d_in[1];   // [DIM, 3*DIM]
    const float* Wproj = (const float*)d_in[2];   // [DIM, DIM]
    float* out = (float*)d_out;                   // [B,S,DIM]

    float* qkv;  cudaGetSymbolAddress((void**)&qkv, g_qkv);
    float* att;  cudaGetSymbolAddress((void**)&att, g_att);
    __nv_bfloat16 *xhi, *xlo, *wqh, *wql, *wph, *wpl, *ahi, *alo;
    cudaGetSymbolAddress((void**)&xhi, g_xhi);
    cudaGetSymbolAddress((void**)&xlo, g_xlo);
    cudaGetSymbolAddress((void**)&wqh, g_wqkvT_hi);
    cudaGetSymbolAddress((void**)&wql, g_wqkvT_lo);
    cudaGetSymbolAddress((void**)&wph, g_wprojT_hi);
    cudaGetSymbolAddress((void**)&wpl, g_wprojT_lo);
    cudaGetSymbolAddress((void**)&ahi, g_atthi);
    cudaGetSymbolAddress((void**)&alo, g_attlo);

    cudaFuncSetAttribute(gemm_mma3, cudaFuncAttributeMaxDynamicSharedMemorySize,
                         GT_SMEM_SZ);

    // 0) split conversions
    {
        int n4 = MTOT * DIM / 4;
        split_rm<<<(n4 + 255) / 256, 256>>>(x, xhi, xlo, n4);
        dim3 tb(32, 8);
        split_tr<<<dim3(QKV_N / 32, DIM / 32), tb>>>(Wqkv, wqh, wql, DIM, QKV_N);
        split_tr<<<dim3(DIM / 32, DIM / 32), tb>>>(Wproj, wph, wpl, DIM, DIM);
    }
    // 1) qkv = x @ Wqkv   [4096,1024]@[1024,3072]
    gemm_mma3<<<dim3(QKV_N / 128, MTOT / 128), 256, GT_SMEM_SZ>>>(
        xhi, xlo, wqh, wql, qkv, MTOT, QKV_N, DIM);
    // 2) attention
    flash_attn<<<dim3(SEQ / 64, NH, BSZ), 128>>>(qkv, att);
    // 3) split attention output, proj GEMM
    {
        int n4 = MTOT * DIM / 4;
        split_rm<<<(n4 + 255) / 256, 256>>>(att, ahi, alo, n4);
    }
    gemm_mma3<<<dim3(DIM / 128, MTOT / 128), 256, GT_SMEM_SZ>>>(
        ahi, alo, wph, wpl, out, MTOT, DIM, DIM);
}

// round 7
// speedup vs baseline: 4.5129x; 2.8448x over previous
#include <cuda_runtime.h>
#include <cuda_bf16.h>
#include <math.h>
#include <stdint.h>

#define BSZ 2
#define SEQ 2048
#define DIM 1024
#define NH  16
#define HDIM 64
#define MTOT (BSZ * SEQ)       // 4096
#define QKV_N (3 * DIM)        // 3072

// ---------------------------------------------------------------------------
// Scratch (module-load allocation, not kernel_launch allocation)
// ---------------------------------------------------------------------------
static __device__ __nv_bfloat16 g_xhi[(size_t)MTOT * DIM];
static __device__ __nv_bfloat16 g_xlo[(size_t)MTOT * DIM];
static __device__ __nv_bfloat16 g_wqkvT_hi[(size_t)QKV_N * DIM]; // [N,K]
static __device__ __nv_bfloat16 g_wqkvT_lo[(size_t)QKV_N * DIM];
static __device__ __nv_bfloat16 g_wprojT_hi[(size_t)DIM * DIM];
static __device__ __nv_bfloat16 g_wprojT_lo[(size_t)DIM * DIM];
static __device__ __nv_bfloat16 g_qkvh[(size_t)MTOT * QKV_N];    // split qkv (q pre-scaled)
static __device__ __nv_bfloat16 g_qkvl[(size_t)MTOT * QKV_N];
static __device__ __nv_bfloat16 g_atth[(size_t)MTOT * DIM];
static __device__ __nv_bfloat16 g_attl[(size_t)MTOT * DIM];

// ---------------------------------------------------------------------------
// Warp MMA / async-copy helpers (sm_80+ baseline — no 'a'-gated features)
// ---------------------------------------------------------------------------
__device__ __forceinline__ uint32_t smem_u32(const void* p) {
    uint32_t a;
    asm("{ .reg .u64 t; cvta.to.shared.u64 t, %1; cvt.u32.u64 %0, t; }"
        : "=r"(a) : "l"(p));
    return a;
}
__device__ __forceinline__ void ldsm_x4(uint32_t addr, uint32_t* r) {
    asm volatile("ldmatrix.sync.aligned.m8n8.x4.shared.b16 {%0,%1,%2,%3}, [%4];"
                 : "=r"(r[0]), "=r"(r[1]), "=r"(r[2]), "=r"(r[3]) : "r"(addr));
}
__device__ __forceinline__ void ldsm_x4_t(uint32_t addr, uint32_t* r) {
    asm volatile("ldmatrix.sync.aligned.m8n8.x4.trans.shared.b16 {%0,%1,%2,%3}, [%4];"
                 : "=r"(r[0]), "=r"(r[1]), "=r"(r[2]), "=r"(r[3]) : "r"(addr));
}
__device__ __forceinline__ void mma_bf16(float* d, const uint32_t* a, const uint32_t* b) {
    asm volatile(
        "mma.sync.aligned.m16n8k16.row.col.f32.bf16.bf16.f32 "
        "{%0,%1,%2,%3}, {%4,%5,%6,%7}, {%8,%9}, {%0,%1,%2,%3};"
        : "+f"(d[0]), "+f"(d[1]), "+f"(d[2]), "+f"(d[3])
        : "r"(a[0]), "r"(a[1]), "r"(a[2]), "r"(a[3]), "r"(b[0]), "r"(b[1]));
}
#define CPA16(dst, src) \
    asm volatile("cp.async.cg.shared.global [%0], [%1], 16;" :: "r"(dst), "l"(src))
#define CPA_COMMIT() asm volatile("cp.async.commit_group;")
#define CPA_WAIT0()  asm volatile("cp.async.wait_group 0;")
#define CPA_WAIT1()  asm volatile("cp.async.wait_group 1;")

__device__ __forceinline__ uint32_t packbf2(float x, float y) {
    __nv_bfloat162 t = __float22bfloat162_rn(make_float2(x, y));
    return *(uint32_t*)&t;
}
// pack hi, compute residual pack
__device__ __forceinline__ void split2(float x, float y, uint32_t& hi, uint32_t& lo) {
    __nv_bfloat162 t = __float22bfloat162_rn(make_float2(x, y));
    hi = *(uint32_t*)&t;
    float rx = x - __low2float(t);
    float ry = y - __high2float(t);
    lo = packbf2(rx, ry);
}

// ---------------------------------------------------------------------------
// Split conversion kernels
// ---------------------------------------------------------------------------
__global__ void split_rm(const float* __restrict__ in, __nv_bfloat16* __restrict__ hi,
                         __nv_bfloat16* __restrict__ lo, int n4) {
    int i = blockIdx.x * 256 + threadIdx.x;
    if (i >= n4) return;
    float4 v = ((const float4*)in)[i];
    uint32_t h0, l0, h1, l1;
    split2(v.x, v.y, h0, l0);
    split2(v.z, v.w, h1, l1);
    ((uint32_t*)hi)[i * 2 + 0] = h0;
    ((uint32_t*)hi)[i * 2 + 1] = h1;
    ((uint32_t*)lo)[i * 2 + 0] = l0;
    ((uint32_t*)lo)[i * 2 + 1] = l1;
}

// in: [K,N] fp32 row-major  ->  out hi/lo: [N,K] bf16 row-major (transposed split)
__global__ void split_tr(const float* __restrict__ in, __nv_bfloat16* __restrict__ hi,
                         __nv_bfloat16* __restrict__ lo, int K, int N) {
    __shared__ float t[32][33];
    int n0 = blockIdx.x * 32, k0 = blockIdx.y * 32;
    int tx = threadIdx.x, ty = threadIdx.y;
#pragma unroll
    for (int i = ty; i < 32; i += 8)
        t[i][tx] = in[(size_t)(k0 + i) * N + n0 + tx];
    __syncthreads();
#pragma unroll
    for (int i = ty; i < 32; i += 8) {
        float x = t[tx][i];   // element (k0+tx, n0+i)
        __nv_bfloat16 h = __float2bfloat16(x);
        size_t idx = (size_t)(n0 + i) * K + k0 + tx;
        hi[idx] = h;
        lo[idx] = __float2bfloat16(x - __bfloat162float(h));
    }
}

// ---------------------------------------------------------------------------
// Split-bf16 mma.sync GEMM: C[M,N] = A[M,K] @ Bt[N,K]^T
// SPLIT=false: write fp32 Cf.  SPLIT=true: write bf16 Chi/Clo, scaling columns
// col < scale_cols by 0.125 (softmax scale folded into q).
// ---------------------------------------------------------------------------
#define GT_ROWP    40
#define GT_TILE_B  (128 * GT_ROWP * 2)         // 10240
#define GT_STAGE_B (4 * GT_TILE_B)             // 40960
#define GT_SMEM_SZ (2 * GT_STAGE_B)            // 81920

template <bool SPLIT>
__global__ __launch_bounds__(256)
void gemm_mma3(const __nv_bfloat16* __restrict__ Ahi, const __nv_bfloat16* __restrict__ Alo,
               const __nv_bfloat16* __restrict__ Bthi, const __nv_bfloat16* __restrict__ Btlo,
               float* __restrict__ Cf, __nv_bfloat16* __restrict__ Chi,
               __nv_bfloat16* __restrict__ Clo, int scale_cols,
               int M, int N, int K) {
    extern __shared__ char smem[];
    const uint32_t sbase = smem_u32(smem);
    const int tid = threadIdx.x;
    const int wid = tid >> 5;
    const int lane = tid & 31;
    const int wm = wid >> 2;
    const int wn = wid & 3;
    const int grp = lane >> 2;
    const int qid = lane & 3;
    const int bm = blockIdx.y * 128;
    const int bn = blockIdx.x * 128;
    const int NC = K >> 5;

    const __nv_bfloat16* srcs[4];
    srcs[0] = Ahi + (size_t)bm * K;
    srcs[1] = Alo + (size_t)bm * K;
    srcs[2] = Bthi + (size_t)bn * K;
    srcs[3] = Btlo + (size_t)bn * K;

    float4 pf[8];
    auto load_g = [&](int c) {
        int k0 = c << 5;
#pragma unroll
        for (int i = 0; i < 8; ++i) {
            int t = i >> 1;
            int f = tid + (i & 1) * 256;
            int r = f >> 2, c8 = (f & 3) << 3;
            pf[i] = *(const float4*)(srcs[t] + (size_t)r * K + k0 + c8);
        }
    };
    auto store_s = [&](int buf) {
        char* dst = smem + buf * GT_STAGE_B;
#pragma unroll
        for (int i = 0; i < 8; ++i) {
            int t = i >> 1;
            int f = tid + (i & 1) * 256;
            int r = f >> 2, c8 = (f & 3) << 3;
            *(float4*)(dst + t * GT_TILE_B + (r * GT_ROWP + c8) * 2) = pf[i];
        }
    };

    float acc[4][4][4];
#pragma unroll
    for (int i = 0; i < 4; ++i)
#pragma unroll
        for (int j = 0; j < 4; ++j)
#pragma unroll
            for (int q = 0; q < 4; ++q) acc[i][j][q] = 0.f;

    const int a_row = wm * 64 + (lane & 15);
    const int a_col = (lane >> 4) << 3;
    const int b_row = wn * 32 + (((lane >> 4) & 1) << 3) + (lane & 7);
    const int b_col = ((lane >> 3) & 1) << 3;

    load_g(0);
    store_s(0);
    __syncthreads();

    for (int c = 0; c < NC; ++c) {
        if (c + 1 < NC) load_g(c + 1);

        const uint32_t st = sbase + (c & 1) * GT_STAGE_B;
        const uint32_t sAh = st;
        const uint32_t sAl = st + GT_TILE_B;
        const uint32_t sBh = st + 2 * GT_TILE_B;
        const uint32_t sBl = st + 3 * GT_TILE_B;

#pragma unroll
        for (int ks = 0; ks < 2; ++ks) {
            uint32_t ah[4][4], al[4][4], bh[2][4], bl[2][4];
#pragma unroll
            for (int mt = 0; mt < 4; ++mt) {
                uint32_t off = ((a_row + mt * 16) * GT_ROWP + ks * 16 + a_col) * 2;
                ldsm_x4(sAh + off, ah[mt]);
                ldsm_x4(sAl + off, al[mt]);
            }
#pragma unroll
            for (int p = 0; p < 2; ++p) {
                uint32_t off = ((b_row + p * 16) * GT_ROWP + ks * 16 + b_col) * 2;
                ldsm_x4(sBh + off, bh[p]);
                ldsm_x4(sBl + off, bl[p]);
            }
#pragma unroll
            for (int mt = 0; mt < 4; ++mt) {
#pragma unroll
                for (int nt = 0; nt < 4; ++nt) {
                    const uint32_t* Bh = &bh[nt >> 1][(nt & 1) * 2];
                    const uint32_t* Bl = &bl[nt >> 1][(nt & 1) * 2];
                    mma_bf16(acc[mt][nt], ah[mt], Bh);
                    mma_bf16(acc[mt][nt], ah[mt], Bl);
                    mma_bf16(acc[mt][nt], al[mt], Bh);
                }
            }
        }

        __syncthreads();
        if (c + 1 < NC) {
            store_s((c + 1) & 1);
            __syncthreads();
        }
    }

#pragma unroll
    for (int mt = 0; mt < 4; ++mt) {
#pragma unroll
        for (int nt = 0; nt < 4; ++nt) {
            int row = bm + wm * 64 + mt * 16 + grp;
            int col = bn + wn * 32 + nt * 8 + qid * 2;
            if (SPLIT) {
                float sc = (col < scale_cols) ? 0.125f : 1.0f;
                uint32_t h0, l0, h1, l1;
                split2(acc[mt][nt][0] * sc, acc[mt][nt][1] * sc, h0, l0);
                split2(acc[mt][nt][2] * sc, acc[mt][nt][3] * sc, h1, l1);
                *(uint32_t*)&Chi[(size_t)row * N + col] = h0;
                *(uint32_t*)&Clo[(size_t)row * N + col] = l0;
                *(uint32_t*)&Chi[(size_t)(row + 8) * N + col] = h1;
                *(uint32_t*)&Clo[(size_t)(row + 8) * N + col] = l1;
            } else {
                *(float2*)&Cf[(size_t)row * N + col] =
                    make_float2(acc[mt][nt][0], acc[mt][nt][1]);
                *(float2*)&Cf[(size_t)(row + 8) * N + col] =
                    make_float2(acc[mt][nt][2], acc[mt][nt][3]);
            }
        }
    }
}

// ---------------------------------------------------------------------------
// Tensor-core flash attention (bf16x3 mma.sync).
// CTA = 128 queries x one (b,h). 256 threads = 8 warps, warp = 16 query rows.
// K/V streamed in 64-key tiles (hi+lo), cp.async double-buffered.
// P fragments built in registers from S accumulators (no smem round trip).
// Output written as split bf16 (feeds proj GEMM directly).
// ---------------------------------------------------------------------------
#define AT_ROWP   72                            // padded row (bf16): 144 B
#define AT_TILE_B (64 * AT_ROWP * 2)            // 9216
#define AT_STAGE_B (4 * AT_TILE_B)              // 36864 (Kh,Kl,Vh,Vl)
#define AT_SMEM   (2 * AT_STAGE_B)              // 73728
#define AT_QBUF   (128 * AT_ROWP * 2)           // 18432 (per Q half)

__global__ __launch_bounds__(256)
void flash_attn_mma(const __nv_bfloat16* __restrict__ qh_,
                    const __nv_bfloat16* __restrict__ ql_,
                    __nv_bfloat16* __restrict__ outh,
                    __nv_bfloat16* __restrict__ outl) {
    extern __shared__ char smem[];
    const uint32_t sb = smem_u32(smem);
    const int tid = threadIdx.x;
    const int wid = tid >> 5;
    const int lane = tid & 31;
    const int grp = lane >> 2;
    const int qid = lane & 3;
    const int qt = blockIdx.x;
    const int h  = blockIdx.y;
    const int b  = blockIdx.z;

    // ---- load Q tile (hi at sb+0, lo at sb+AT_QBUF) ----
    {
        const __nv_bfloat16* qgh = qh_ + ((size_t)(b * SEQ + qt * 128)) * QKV_N + h * HDIM;
        const __nv_bfloat16* qgl = ql_ + ((size_t)(b * SEQ + qt * 128)) * QKV_N + h * HDIM;
#pragma unroll
        for (int j = 0; j < 4; ++j) {
            int f = tid + j * 256;            // 0..1023
            int r = f >> 3, c8 = (f & 7) << 3;
            uint32_t so = (uint32_t)(r * AT_ROWP + c8) * 2;
            CPA16(sb + so, qgh + (size_t)r * QKV_N + c8);
            CPA16(sb + AT_QBUF + so, qgl + (size_t)r * QKV_N + c8);
        }
        CPA_COMMIT();
        CPA_WAIT0();
        __syncthreads();
    }

    // ---- extract Q fragments ----
    uint32_t qfh[4][4], qfl[4][4];
    {
        const int a_row = wid * 16 + (lane & 15);
        const int a_col = (lane >> 4) << 3;
#pragma unroll
        for (int kb = 0; kb < 4; ++kb) {
            uint32_t off = (uint32_t)(a_row * AT_ROWP + kb * 16 + a_col) * 2;
            ldsm_x4(sb + off, qfh[kb]);
            ldsm_x4(sb + AT_QBUF + off, qfl[kb]);
        }
    }
    __syncthreads();   // Q region will be overwritten by K/V stages

    // ---- K/V tile async loads ----
    const __nv_bfloat16* kbh = qh_ + (size_t)(b * SEQ) * QKV_N + DIM + h * HDIM;
    const __nv_bfloat16* kbl = ql_ + (size_t)(b * SEQ) * QKV_N + DIM + h * HDIM;
    const __nv_bfloat16* vbh = kbh + DIM;
    const __nv_bfloat16* vbl = kbl + DIM;
    auto issue = [&](int kt) {
        uint32_t bo = sb + (kt & 1) * AT_STAGE_B;
        size_t rb = (size_t)(kt * 64);
#pragma unroll
        for (int j = 0; j < 2; ++j) {
            int f = tid + j * 256;            // 0..511
            int r = f >> 3, c8 = (f & 7) << 3;
            uint32_t so = (uint32_t)(r * AT_ROWP + c8) * 2;
            size_t go = (rb + r) * QKV_N + c8;
            CPA16(bo + so,                 kbh + go);
            CPA16(bo + AT_TILE_B + so,     kbl + go);
            CPA16(bo + 2 * AT_TILE_B + so, vbh + go);
            CPA16(bo + 3 * AT_TILE_B + so, vbl + go);
        }
        CPA_COMMIT();
    };

    float m0 = -INFINITY, m1 = -INFINITY, l0 = 0.f, l1 = 0.f;
    float o[8][4];
#pragma unroll
    for (int n = 0; n < 8; ++n)
#pragma unroll
        for (int q = 0; q < 4; ++q) o[n][q] = 0.f;

    const int b_row = (((lane >> 4) & 1) << 3) + (lane & 7);
    const int b_col = ((lane >> 3) & 1) << 3;
    const int v_row = lane & 15;
    const int v_col = (lane >> 4) << 3;

    issue(0);

    for (int kt = 0; kt < SEQ / 64; ++kt) {
        if (kt + 1 < SEQ / 64) { issue(kt + 1); CPA_WAIT1(); }
        else                   { CPA_WAIT0(); }
        __syncthreads();

        const uint32_t st = sb + (kt & 1) * AT_STAGE_B;

        // ---- S = Q @ K^T (bf16x3) ----
        float s[8][4];
#pragma unroll
        for (int n = 0; n < 8; ++n)
#pragma unroll
            for (int q = 0; q < 4; ++q) s[n][q] = 0.f;

#pragma unroll
        for (int kb = 0; kb < 4; ++kb) {
#pragma unroll
            for (int nb2 = 0; nb2 < 4; ++nb2) {
                uint32_t off = (uint32_t)((nb2 * 16 + b_row) * AT_ROWP + kb * 16 + b_col) * 2;
                uint32_t bh[4], bl[4];
                ldsm_x4(st + off, bh);
                ldsm_x4(st + AT_TILE_B + off, bl);
#pragma unroll
                for (int hf = 0; hf < 2; ++hf) {
                    int n8 = nb2 * 2 + hf;
                    mma_bf16(s[n8], qfh[kb], &bh[hf * 2]);
                    mma_bf16(s[n8], qfh[kb], &bl[hf * 2]);
                    mma_bf16(s[n8], qfl[kb], &bh[hf * 2]);
                }
            }
        }

        // ---- online softmax ----
        float mx0 = -INFINITY, mx1 = -INFINITY;
#pragma unroll
        for (int n = 0; n < 8; ++n) {
            mx0 = fmaxf(mx0, fmaxf(s[n][0], s[n][1]));
            mx1 = fmaxf(mx1, fmaxf(s[n][2], s[n][3]));
        }
        mx0 = fmaxf(mx0, __shfl_xor_sync(0xffffffffu, mx0, 1));
        mx0 = fmaxf(mx0, __shfl_xor_sync(0xffffffffu, mx0, 2));
        mx1 = fmaxf(mx1, __shfl_xor_sync(0xffffffffu, mx1, 1));
        mx1 = fmaxf(mx1, __shfl_xor_sync(0xffffffffu, mx1, 2));
        float mn0 = fmaxf(m0, mx0), mn1 = fmaxf(m1, mx1);
        float c0 = __expf(m0 - mn0), c1 = __expf(m1 - mn1);
        float rs0 = 0.f, rs1 = 0.f;
#pragma unroll
        for (int n = 0; n < 8; ++n) {
            s[n][0] = __expf(s[n][0] - mn0); rs0 += s[n][0];
            s[n][1] = __expf(s[n][1] - mn0); rs0 += s[n][1];
            s[n][2] = __expf(s[n][2] - mn1); rs1 += s[n][2];
            s[n][3] = __expf(s[n][3] - mn1); rs1 += s[n][3];
        }
        rs0 += __shfl_xor_sync(0xffffffffu, rs0, 1);
        rs0 += __shfl_xor_sync(0xffffffffu, rs0, 2);
        rs1 += __shfl_xor_sync(0xffffffffu, rs1, 1);
        rs1 += __shfl_xor_sync(0xffffffffu, rs1, 2);
        l0 = l0 * c0 + rs0;  l1 = l1 * c1 + rs1;
        m0 = mn0;            m1 = mn1;
#pragma unroll
        for (int n = 0; n < 8; ++n) {
            o[n][0] *= c0; o[n][1] *= c0;
            o[n][2] *= c1; o[n][3] *= c1;
        }

        // ---- P fragments (registers only) ----
        uint32_t ph[4][4], pl[4][4];
#pragma unroll
        for (int kb = 0; kb < 4; ++kb) {
            split2(s[2 * kb][0],     s[2 * kb][1],     ph[kb][0], pl[kb][0]);
            split2(s[2 * kb][2],     s[2 * kb][3],     ph[kb][1], pl[kb][1]);
            split2(s[2 * kb + 1][0], s[2 * kb + 1][1], ph[kb][2], pl[kb][2]);
            split2(s[2 * kb + 1][2], s[2 * kb + 1][3], ph[kb][3], pl[kb][3]);
        }

        // ---- O += P @ V (bf16x3, V via ldmatrix.trans) ----
        const uint32_t vt = st + 2 * AT_TILE_B;
#pragma unroll
        for (int kb = 0; kb < 4; ++kb) {
#pragma unroll
            for (int nb2 = 0; nb2 < 4; ++nb2) {
                uint32_t off = (uint32_t)((kb * 16 + v_row) * AT_ROWP + nb2 * 16 + v_col) * 2;
                uint32_t vh[4], vl[4];
                ldsm_x4_t(vt + off, vh);
                ldsm_x4_t(vt + AT_TILE_B + off, vl);
#pragma unroll
                for (int hf = 0; hf < 2; ++hf) {
                    int n8 = nb2 * 2 + hf;
                    mma_bf16(o[n8], ph[kb], &vh[hf * 2]);
                    mma_bf16(o[n8], ph[kb], &vl[hf * 2]);
                    mma_bf16(o[n8], pl[kb], &vh[hf * 2]);
                }
            }
        }
        __syncthreads();
    }

    // ---- epilogue: normalize, split bf16, write ----
    {
        float inv0 = 1.f / l0, inv1 = 1.f / l1;
        size_t r0 = (size_t)(b * SEQ + qt * 128 + wid * 16 + grp);
#pragma unroll
        for (int n = 0; n < 8; ++n) {
            int col = h * HDIM + n * 8 + qid * 2;
            uint32_t h0, lo0, h1, lo1;
            split2(o[n][0] * inv0, o[n][1] * inv0, h0, lo0);
            split2(o[n][2] * inv1, o[n][3] * inv1, h1, lo1);
            *(uint32_t*)&outh[r0 * DIM + col] = h0;
            *(uint32_t*)&outl[r0 * DIM + col] = lo0;
            *(uint32_t*)&outh[(r0 + 8) * DIM + col] = h1;
            *(uint32_t*)&outl[(r0 + 8) * DIM + col] = lo1;
        }
    }
}

// ---------------------------------------------------------------------------
extern "C" void kernel_launch(void* const* d_in, const int* in_sizes, int n_in,
                              void* d_out, int out_size) {
    const float* x     = (const float*)d_in[0];   // [B,S,DIM]
    const float* Wqkv  = (const float*)d_in[1];   // [DIM, 3*DIM]
    const float* Wproj = (const float*)d_in[2];   // [DIM, DIM]
    float* out = (float*)d_out;                   // [B,S,DIM]

    __nv_bfloat16 *xhi, *xlo, *wqh, *wql, *wph, *wpl, *qkvh, *qkvl, *atth, *attl;
    cudaGetSymbolAddress((void**)&xhi, g_xhi);
    cudaGetSymbolAddress((void**)&xlo, g_xlo);
    cudaGetSymbolAddress((void**)&wqh, g_wqkvT_hi);
    cudaGetSymbolAddress((void**)&wql, g_wqkvT_lo);
    cudaGetSymbolAddress((void**)&wph, g_wprojT_hi);
    cudaGetSymbolAddress((void**)&wpl, g_wprojT_lo);
    cudaGetSymbolAddress((void**)&qkvh, g_qkvh);
    cudaGetSymbolAddress((void**)&qkvl, g_qkvl);
    cudaGetSymbolAddress((void**)&atth, g_atth);
    cudaGetSymbolAddress((void**)&attl, g_attl);

    cudaFuncSetAttribute(gemm_mma3<true>, cudaFuncAttributeMaxDynamicSharedMemorySize,
                         GT_SMEM_SZ);
    cudaFuncSetAttribute(gemm_mma3<false>, cudaFuncAttributeMaxDynamicSharedMemorySize,
                         GT_SMEM_SZ);
    cudaFuncSetAttribute(flash_attn_mma, cudaFuncAttributeMaxDynamicSharedMemorySize,
                         AT_SMEM);

    // 0) split conversions
    {
        int n4 = MTOT * DIM / 4;
        split_rm<<<(n4 + 255) / 256, 256>>>(x, xhi, xlo, n4);
        dim3 tb(32, 8);
        split_tr<<<dim3(QKV_N / 32, DIM / 32), tb>>>(Wqkv, wqh, wql, DIM, QKV_N);
        split_tr<<<dim3(DIM / 32, DIM / 32), tb>>>(Wproj, wph, wpl, DIM, DIM);
    }
    // 1) qkv = x @ Wqkv  -> split bf16, q columns pre-scaled by 1/8
    gemm_mma3<true><<<dim3(QKV_N / 128, MTOT / 128), 256, GT_SMEM_SZ>>>(
        xhi, xlo, wqh, wql, nullptr, qkvh, qkvl, DIM, MTOT, QKV_N, DIM);
    // 2) tensor-core flash attention -> split bf16 att
    flash_attn_mma<<<dim3(SEQ / 128, NH, BSZ), 256, AT_SMEM>>>(qkvh, qkvl, atth, attl);
    // 3) out = att @ Wproj (fp32 out)
    gemm_mma3<false><<<dim3(DIM / 128, MTOT / 128), 256, GT_SMEM_SZ>>>(
        atth, attl, wph, wpl, out, nullptr, nullptr, 0, MTOT, DIM, DIM);
}